// round 9
// baseline (speedup 1.0000x reference)
#include <cuda_runtime.h>

// Problem constants: x,y are (1,1,192,192,192) f32.
#define Wd 192
#define Hd 192
#define Dd 192
#define NVOX (Wd*Hd*Dd)          // 7,077,888
#define N4   (NVOX/4)            // 1,769,472 (float4 quads)
#define N8   (NVOX/8)            // 884,736   (8-voxel segments)

#define RED_BLOCKS 1152
#define RED_THREADS 512
#define RED_ITERS 3
#define RED_STRIDE (RED_BLOCKS*RED_THREADS)   // 589,824 quads ; *3 == N4 exactly
// RED_STRIDE*4 / (192*192) == 64 -> each iter advances exactly 64 z-planes:
// w, h (and gx*, gy) are loop-invariant; d increases by 64 per iter.

#define SAMP_THREADS 256
#define SAMP_BLOCKS (N8 / SAMP_THREADS)       // 3456 exactly

// Scratch (no allocation allowed in kernel_launch).
__device__ float g_part[RED_BLOCKS][8];
__device__ float g_t[3];
__device__ unsigned g_count;   // zero at load; reset by last block each run

static __device__ __forceinline__ float warp_sum(float v) {
    #pragma unroll
    for (int o = 16; o > 0; o >>= 1) v += __shfl_down_sync(0xffffffffu, v, o);
    return v;
}

// ---------------------------------------------------------------------------
// Kernel 1: per-block partial sums of 8 quantities + fused final reduce in the
// last finished block. Quantities:
//  [0]=sum x, [1]=sum x*gx, [2]=sum x*gy, [3]=sum x*gz, [4..7] same for y.
// Exact tiling: RED_BLOCKS*RED_THREADS*RED_ITERS == N4 (no bounds checks).
// ---------------------------------------------------------------------------
__global__ __launch_bounds__(RED_THREADS) void reduce_kernel(
    const float* __restrict__ x, const float* __restrict__ y)
{
    const float step = 2.0f / (float)(Wd - 1);
    float a[8];
    #pragma unroll
    for (int i = 0; i < 8; i++) a[i] = 0.0f;

    const float4* __restrict__ x4 = (const float4*)x;
    const float4* __restrict__ y4 = (const float4*)y;

    int j0 = blockIdx.x * RED_THREADS + threadIdx.x;

    // Loop-invariant coordinates (stride == 64 whole z-planes).
    int e  = j0 * 4;
    int w  = e % Wd;
    int hd = e / Wd;
    int h  = hd % Hd;
    int d0 = hd / Hd;

    float gx0 = fmaf((float)(w+0), step, -1.0f);
    float gx1 = fmaf((float)(w+1), step, -1.0f);
    float gx2 = fmaf((float)(w+2), step, -1.0f);
    float gx3 = fmaf((float)(w+3), step, -1.0f);
    float gy  = fmaf((float)h, step, -1.0f);

    // Front-batched loads for MLP (6 independent LDG.128 in flight).
    float4 vx[RED_ITERS], vy[RED_ITERS];
    #pragma unroll
    for (int i = 0; i < RED_ITERS; i++) {
        vx[i] = __ldg(&x4[j0 + i * RED_STRIDE]);
        vy[i] = __ldg(&y4[j0 + i * RED_STRIDE]);
    }

    #pragma unroll
    for (int i = 0; i < RED_ITERS; i++) {
        float gz = fmaf((float)(d0 + 64 * i), step, -1.0f);

        float sx = (vx[i].x + vx[i].y) + (vx[i].z + vx[i].w);
        a[0] += sx;
        a[1] += vx[i].x*gx0 + vx[i].y*gx1 + vx[i].z*gx2 + vx[i].w*gx3;
        a[2] += sx * gy;
        a[3] += sx * gz;

        float sy = (vy[i].x + vy[i].y) + (vy[i].z + vy[i].w);
        a[4] += sy;
        a[5] += vy[i].x*gx0 + vy[i].y*gx1 + vy[i].z*gx2 + vy[i].w*gx3;
        a[6] += sy * gy;
        a[7] += sy * gz;
    }

    __shared__ float sh[16][8];   // [warp][quantity]  (512 thr = 16 warps)
    int lane = threadIdx.x & 31;
    int warp = threadIdx.x >> 5;
    #pragma unroll
    for (int q = 0; q < 8; q++) {
        float v = warp_sum(a[q]);
        if (lane == 0) sh[warp][q] = v;
    }
    __syncthreads();
    if (warp == 0) {
        #pragma unroll
        for (int q = 0; q < 8; q++) {
            float v = (lane < 16) ? sh[lane][q] : 0.0f;
            v = warp_sum(v);
            if (lane == 0) g_part[blockIdx.x][q] = v;
        }
    }

    // ---- fused finalize: last finished block reduces the partials ----
    __shared__ bool is_last;
    __threadfence();
    if (threadIdx.x == 0)
        is_last = (atomicAdd(&g_count, 1u) == (unsigned)(RED_BLOCKS - 1));
    __syncthreads();
    if (!is_last) return;
    __threadfence();

    {
        __shared__ float s[8];
        int q = warp;                   // warps 0..7 handle the 8 quantities
        if (q < 8) {
            float acc = 0.0f;
            for (int i = lane; i < RED_BLOCKS; i += 32) acc += g_part[i][q];
            acc = warp_sum(acc);
            if (lane == 0) s[q] = acc;
        }
        __syncthreads();
        if (threadIdx.x == 0) {
            float inv_sx = 1.0f / s[0];
            float inv_sy = 1.0f / s[4];
            g_t[0] = s[1] * inv_sx - s[5] * inv_sy;
            g_t[1] = s[2] * inv_sx - s[6] * inv_sy;
            g_t[2] = s[3] * inv_sx - s[7] * inv_sy;
            g_count = 0;                // reset for next graph replay
        }
    }
}

// ---------------------------------------------------------------------------
// Kernel 2: write grid = base + t and transformed = trilinear(x, grid).
// 8 voxels (along w) per thread: per-segment (y/z floors, rb, qq, fast-path
// check) cost is amortized over 8 outputs and each corner row needs only
// 2xLDG.128 + 1 scalar to cover 9 taps (1.5 LDG/voxel vs 2 before).
// Fast paths are validated against the exactly-computed per-voxel indices so
// results are bitwise identical to the scalar path (same FP tap ordering as
// the round-7 passing kernel).
// ---------------------------------------------------------------------------
__global__ __launch_bounds__(SAMP_THREADS, 4) void sample_kernel(
    const float* __restrict__ vol,
    float* __restrict__ out_t,      // NVOX floats
    float* __restrict__ out_g)      // NVOX*3 floats
{
    int j = blockIdx.x * SAMP_THREADS + threadIdx.x;   // segment index, exact

    const float step = 2.0f / (float)(Wd - 1);
    const float tx = g_t[0], ty = g_t[1], tz = g_t[2];

    int e  = j * 8;
    int w0 = e % Wd;                 // multiple of 8 (8 | 192)
    int hd = e / Wd;
    int h  = hd % Hd;
    int d  = hd / Hd;

    float gy = fmaf((float)h, step, -1.0f);
    float gz = fmaf((float)d, step, -1.0f);
    float goy = gy + ty;
    float goz = gz + tz;

    float gox[8];
    #pragma unroll
    for (int k = 0; k < 8; k++)
        gox[k] = fmaf((float)(w0 + k), step, -1.0f) + tx;

    // Early streaming grid stores (depend only on coords + t): 24 floats.
    {
        float4* g4 = (float4*)(out_g + (long)e * 3);   // e*3 = j*24, 16B-aligned
        __stcs(g4 + 0, make_float4(gox[0], goy, goz, gox[1]));
        __stcs(g4 + 1, make_float4(goy, goz, gox[2], goy));
        __stcs(g4 + 2, make_float4(goz, gox[3], goy, goz));
        __stcs(g4 + 3, make_float4(gox[4], goy, goz, gox[5]));
        __stcs(g4 + 4, make_float4(goy, goz, gox[6], goy));
        __stcs(g4 + 5, make_float4(goz, gox[7], goy, goz));
    }

    // y/z sample coords shared by all 8 voxels.
    float iy = (goy + 1.0f) * 0.5f * (float)(Hd - 1);
    float iz = (goz + 1.0f) * 0.5f * (float)(Dd - 1);
    float iy0f = floorf(iy), iz0f = floorf(iz);
    float wy = iy - iy0f,    wz = iz - iz0f;
    int iy0 = (int)iy0f, iz0 = (int)iz0f;
    int iy1 = iy0 + 1,   iz1 = iz0 + 1;

    float vy0 = (iy0 >= 0 && iy0 < Hd) ? 1.0f : 0.0f;
    float vy1 = (iy1 >= 0 && iy1 < Hd) ? 1.0f : 0.0f;
    float vz0 = (iz0 >= 0 && iz0 < Dd) ? 1.0f : 0.0f;
    float vz1 = (iz1 >= 0 && iz1 < Dd) ? 1.0f : 0.0f;
    int cy0 = min(max(iy0, 0), Hd - 1);
    int cy1 = min(max(iy1, 0), Hd - 1);
    int cz0 = min(max(iz0, 0), Dd - 1);
    int cz1 = min(max(iz1, 0), Dd - 1);

    int rb[4];
    rb[0] = cz0 * (Hd * Wd) + cy0 * Wd;   // b00
    rb[1] = cz0 * (Hd * Wd) + cy1 * Wd;   // b01
    rb[2] = cz1 * (Hd * Wd) + cy0 * Wd;   // b10
    rb[3] = cz1 * (Hd * Wd) + cy1 * Wd;   // b11

    float qq[4];
    qq[0] = (1.0f - wz) * (1.0f - wy) * vz0 * vy0;
    qq[1] = (1.0f - wz) * wy          * vz0 * vy1;
    qq[2] = wz          * (1.0f - wy) * vz1 * vy0;
    qq[3] = wz          * wy          * vz1 * vy1;

    // Per-voxel x coordinates (exact, same arithmetic as the reference path).
    float wxa[8], wxb[8];
    int   cx0a[8], cx1a[8];
    #pragma unroll
    for (int k = 0; k < 8; k++) {
        float ix = (gox[k] + 1.0f) * 0.5f * (float)(Wd - 1);
        float ix0f = floorf(ix);
        float wx = ix - ix0f;
        int ix0 = (int)ix0f;
        int ix1 = ix0 + 1;
        float vx0 = (ix0 >= 0 && ix0 < Wd) ? 1.0f : 0.0f;
        float vx1 = (ix1 >= 0 && ix1 < Wd) ? 1.0f : 0.0f;
        cx0a[k] = min(max(ix0, 0), Wd - 1);
        cx1a[k] = min(max(ix1, 0), Wd - 1);
        wxa[k] = (1.0f - wx) * vx0;
        wxb[k] = wx * vx1;
    }

    int ce7 = min(w0 + 8, Wd - 1);   // expected clamped cx1 for k=7, shift 0
    int cm0 = max(w0 - 1, 0);        // expected clamped cx0 for k=0, shift -1

    bool f0 = (cx1a[7] == ce7);
    bool fm = (cx0a[0] == cm0);
    #pragma unroll
    for (int k = 0; k < 8; k++) {
        f0 = f0 & (cx0a[k] == w0 + k);
        fm = fm & (cx1a[k] == w0 + k);
    }
    #pragma unroll
    for (int k = 0; k < 7; k++) f0 = f0 & (cx1a[k] == w0 + k + 1);
    #pragma unroll
    for (int k = 1; k < 8; k++) fm = fm & (cx0a[k] == w0 + k - 1);

    float tr[8];
    #pragma unroll
    for (int k = 0; k < 8; k++) tr[k] = 0.0f;

    if (f0) {
        // Window per row: P[0..8] = vol[rb + w0 .. w0+7], vol[rb + ce7]
        #pragma unroll
        for (int r = 0; r < 4; r++) {
            float4 A0 = __ldg((const float4*)(vol + rb[r] + w0));
            float4 A1 = __ldg((const float4*)(vol + rb[r] + w0 + 4));
            float  Rs = __ldg(vol + rb[r] + ce7);
            float P[9] = {A0.x, A0.y, A0.z, A0.w, A1.x, A1.y, A1.z, A1.w, Rs};
            #pragma unroll
            for (int k = 0; k < 8; k++)
                tr[k] += qq[r] * (P[k] * wxa[k] + P[k+1] * wxb[k]);
        }
    } else if (fm) {
        // Window per row: P[0..8] = vol[rb + cm0], vol[rb + w0 .. w0+7]
        #pragma unroll
        for (int r = 0; r < 4; r++) {
            float  Ls = __ldg(vol + rb[r] + cm0);
            float4 A0 = __ldg((const float4*)(vol + rb[r] + w0));
            float4 A1 = __ldg((const float4*)(vol + rb[r] + w0 + 4));
            float P[9] = {Ls, A0.x, A0.y, A0.z, A0.w, A1.x, A1.y, A1.z, A1.w};
            #pragma unroll
            for (int k = 0; k < 8; k++)
                tr[k] += qq[r] * (P[k] * wxa[k] + P[k+1] * wxb[k]);
        }
    } else {
        // General fallback: exact scalar gathers (rare: |shift| >= 1 or
        // inconsistent rounding flips).
        #pragma unroll
        for (int k = 0; k < 8; k++) {
            int cx0 = cx0a[k], cx1 = cx1a[k];
            #pragma unroll
            for (int r = 0; r < 4; r++) {
                float v = __ldg(&vol[rb[r] + cx0]) * wxa[k]
                        + __ldg(&vol[rb[r] + cx1]) * wxb[k];
                tr[k] += qq[r] * v;
            }
        }
    }

    // Streaming stores (output never re-read; keep x resident in L2).
    float4* o4 = (float4*)out_t + 2 * j;
    __stcs(o4 + 0, make_float4(tr[0], tr[1], tr[2], tr[3]));
    __stcs(o4 + 1, make_float4(tr[4], tr[5], tr[6], tr[7]));
}

// ---------------------------------------------------------------------------
extern "C" void kernel_launch(void* const* d_in, const int* in_sizes, int n_in,
                              void* d_out, int out_size)
{
    const float* x = (const float*)d_in[0];
    const float* y = (const float*)d_in[1];
    float* out_transformed = (float*)d_out;            // NVOX floats
    float* out_grid        = (float*)d_out + NVOX;     // NVOX*3 floats

    reduce_kernel<<<RED_BLOCKS, RED_THREADS>>>(x, y);
    sample_kernel<<<SAMP_BLOCKS, SAMP_THREADS>>>(x, out_transformed, out_grid);
}